// round 4
// baseline (speedup 1.0000x reference)
#include <cuda_runtime.h>
#include <cuda_bf16.h>
#include <math_constants.h>

// Problem constants (fixed by the dataset)
constexpr int NN = 100000;   // nodes
constexpr int EE = 1600000;  // edges
constexpr int DD = 128;      // model dim
constexpr int HH = 8;        // heads
// DH = 16, M = 3

// ---------------- scratch (static device globals; no allocation) -------------
__device__ float g_Q[NN * DD];
__device__ float g_K[NN * DD];
__device__ float g_V[NN * DD];
__device__ int   g_deg[NN];
__device__ int   g_rowptr[NN + 1];
__device__ int   g_cursor[NN];
__device__ int2  g_edge[EE];          // (eid, src) packed
__device__ float g_max[NN * HH];
__device__ float g_sum[NN * HH];
__device__ int   g_bsum[128];

// ---------------- 3xTF32 helpers ---------------------------------------------
__device__ __forceinline__ void split_tf32(float a, unsigned& hi, unsigned& lo) {
    float h, l;
    asm("cvt.rna.tf32.f32 %0, %1;" : "=f"(h) : "f"(a));
    l = a - h;
    asm("cvt.rna.tf32.f32 %0, %1;" : "=f"(l) : "f"(l));
    hi = __float_as_uint(h);
    lo = __float_as_uint(l);
}

__device__ __forceinline__ void mma_tf32(float c[4], const unsigned a[4],
                                         const unsigned b[2]) {
    asm volatile(
        "mma.sync.aligned.m16n8k8.row.col.f32.tf32.tf32.f32 "
        "{%0,%1,%2,%3}, {%4,%5,%6,%7}, {%8,%9}, {%0,%1,%2,%3};"
        : "+f"(c[0]), "+f"(c[1]), "+f"(c[2]), "+f"(c[3])
        : "r"(a[0]), "r"(a[1]), "r"(a[2]), "r"(a[3]), "r"(b[0]), "r"(b[1]));
}

// ---------------- QKV GEMM (tensor core, 3xTF32) ------------------------------
// Block tile 128x128, full K=128 resident in smem. 256 threads = 8 warps in a
// 4(M) x 2(N) grid; warp tile 32x64 = 2 m-tiles x 8 n-tiles of m16n8k8.
constexpr int XS = 132;   // xs row stride (A-frag loads conflict-free: 4*row+k)
constexpr int WS = 136;   // ws row stride (B-frag loads conflict-free: 8*k+col)
constexpr int GEMM_SMEM = (128 * XS + 128 * WS) * 4;   // ~134 KB

__global__ __launch_bounds__(256) void qkv_gemm_tc(
    const float* __restrict__ x,
    const float* __restrict__ Wq, const float* __restrict__ bq,
    const float* __restrict__ Wk, const float* __restrict__ bk,
    const float* __restrict__ Wv, const float* __restrict__ bv,
    int n)
{
    extern __shared__ float smem[];
    float* xs = smem;               // [128 rows][XS]  (row-major, k contiguous)
    float* ws = smem + 128 * XS;    // [128 k][WS]     (k-major, col contiguous)

    const int tid  = threadIdx.x;
    const int lane = tid & 31;
    const int wid  = tid >> 5;
    const int warpM = wid & 3;      // 0..3  -> 32 rows each
    const int warpN = wid >> 2;     // 0..1  -> 64 cols each
    const int row0 = blockIdx.x * 128;

    // load x tile [128][128]; OOB rows -> 0
    for (int i = tid; i < 128 * 32; i += 256) {
        int r = i >> 5, c = (i & 31) << 2;
        float4 v = make_float4(0.f, 0.f, 0.f, 0.f);
        if (row0 + r < n) v = *(const float4*)(x + (size_t)(row0 + r) * DD + c);
        *(float4*)(&xs[r * XS + c]) = v;
    }

    const float* Ws[3] = {Wq, Wk, Wv};
    const float* Bs[3] = {bq, bk, bv};
    float*       Os[3] = {g_Q, g_K, g_V};

    const int gidx = lane >> 2;     // 0..7
    const int tidx = lane & 3;      // 0..3

    for (int w = 0; w < 3; ++w) {
        __syncthreads();   // previous readers of ws done
        for (int i = tid; i < 128 * 32; i += 256) {
            int r = i >> 5, c = (i & 31) << 2;
            *(float4*)(&ws[r * WS + c]) =
                *(const float4*)(Ws[w] + (size_t)r * DD + c);
        }
        __syncthreads();

        float C[2][8][4];
#pragma unroll
        for (int mt = 0; mt < 2; ++mt)
#pragma unroll
            for (int nt = 0; nt < 8; ++nt)
#pragma unroll
                for (int q = 0; q < 4; ++q) C[mt][nt][q] = 0.f;

#pragma unroll
        for (int k8 = 0; k8 < 16; ++k8) {
            const int kb = k8 * 8;

            unsigned ah[2][4], al[2][4];
#pragma unroll
            for (int mt = 0; mt < 2; ++mt) {
                int row = warpM * 32 + mt * 16 + gidx;
                int col = kb + tidx;
                split_tf32(xs[row * XS + col],           ah[mt][0], al[mt][0]);
                split_tf32(xs[(row + 8) * XS + col],     ah[mt][1], al[mt][1]);
                split_tf32(xs[row * XS + col + 4],       ah[mt][2], al[mt][2]);
                split_tf32(xs[(row + 8) * XS + col + 4], ah[mt][3], al[mt][3]);
            }

            unsigned bh[8][2], bl[8][2];
#pragma unroll
            for (int nt = 0; nt < 8; ++nt) {
                int colb = warpN * 64 + nt * 8 + gidx;
                int krow = kb + tidx;
                split_tf32(ws[krow * WS + colb],       bh[nt][0], bl[nt][0]);
                split_tf32(ws[(krow + 4) * WS + colb], bh[nt][1], bl[nt][1]);
            }

#pragma unroll
            for (int mt = 0; mt < 2; ++mt)
#pragma unroll
                for (int nt = 0; nt < 8; ++nt) {
                    mma_tf32(C[mt][nt], ah[mt], bh[nt]);   // hi*hi
                    mma_tf32(C[mt][nt], al[mt], bh[nt]);   // lo*hi
                    mma_tf32(C[mt][nt], ah[mt], bl[nt]);   // hi*lo
                }
        }

        // epilogue: bias add + store (float2 per fragment row)
        float* O = Os[w];
        const float* B = Bs[w];
#pragma unroll
        for (int nt = 0; nt < 8; ++nt) {
            int col = warpN * 64 + nt * 8 + 2 * tidx;
            float b0 = __ldg(B + col);
            float b1 = __ldg(B + col + 1);
#pragma unroll
            for (int mt = 0; mt < 2; ++mt) {
                int r0 = row0 + warpM * 32 + mt * 16 + gidx;
                int r1 = r0 + 8;
                if (r0 < n) {
                    float2 o = make_float2(C[mt][nt][0] + b0, C[mt][nt][1] + b1);
                    *(float2*)(O + (size_t)r0 * DD + col) = o;
                }
                if (r1 < n) {
                    float2 o = make_float2(C[mt][nt][2] + b0, C[mt][nt][3] + b1);
                    *(float2*)(O + (size_t)r1 * DD + col) = o;
                }
            }
        }
    }
}

// ---------------- CSR construction -------------------------------------------
__global__ void zero_deg(int n) {
    int i = blockIdx.x * blockDim.x + threadIdx.x;
    if (i < n) g_deg[i] = 0;
}

__global__ void hist_kernel(const int* __restrict__ dst, int E) {
    int i = blockIdx.x * blockDim.x + threadIdx.x;
    if (i < E) atomicAdd(&g_deg[dst[i]], 1);
}

// block-local exclusive scan; block sums to g_bsum
__global__ __launch_bounds__(1024) void scan1(int n) {
    __shared__ int sm[1024];
    const int t = threadIdx.x;
    const int i = blockIdx.x * 1024 + t;
    int v = (i < n) ? g_deg[i] : 0;
    sm[t] = v;
    __syncthreads();
    for (int off = 1; off < 1024; off <<= 1) {
        int u = (t >= off) ? sm[t - off] : 0;
        __syncthreads();
        sm[t] += u;
        __syncthreads();
    }
    if (i < n) g_rowptr[i] = sm[t] - v;  // local exclusive
    if (t == 1023) g_bsum[blockIdx.x] = sm[t];
}

// fused: each block computes its own offset from g_bsum, applies it
__global__ __launch_bounds__(1024) void scan3(int n, int E) {
    __shared__ int soff;
    const int t = threadIdx.x;
    if (t == 0) soff = 0;
    __syncthreads();
    int acc = 0;
    for (int j = t; j < blockIdx.x; j += 1024) acc += g_bsum[j];
    if (acc) atomicAdd(&soff, acc);
    __syncthreads();
    const int i = blockIdx.x * 1024 + t;
    if (i < n) {
        int r = g_rowptr[i] + soff;
        g_rowptr[i] = r;
        g_cursor[i] = r;
    }
    if (i == 0) g_rowptr[n] = E;
}

__global__ void scatter_kernel(const int* __restrict__ src,
                               const int* __restrict__ dst, int E) {
    int i = blockIdx.x * blockDim.x + threadIdx.x;
    if (i < E) {
        int p = atomicAdd(&g_cursor[dst[i]], 1);
        g_edge[p] = make_int2(i, src[i]);
    }
}

// ---------------- per-node online-softmax attention --------------------------
// One warp per node. lane -> (head = lane/4, dim-quad = lane%4).
__global__ __launch_bounds__(256) void node_attn(
    const float* __restrict__ pi, const float* __restrict__ view_w,
    float* __restrict__ ns_out, float* __restrict__ attn_out, int n)
{
    int warp = (blockIdx.x * blockDim.x + threadIdx.x) >> 5;
    if (warp >= n) return;
    const int lane = threadIdx.x & 31;
    const int h = lane >> 2;
    const int dsub = lane & 3;
    const int nd = warp;

    const float4* Q4 = (const float4*)g_Q;
    const float4* K4 = (const float4*)g_K;
    const float4* V4 = (const float4*)g_V;

    const float4 qv = Q4[nd * 32 + h * 4 + dsub];
    const float p0 = pi[nd * 24 + h * 3 + 0];
    const float p1 = pi[nd * 24 + h * 3 + 1];
    const float p2 = pi[nd * 24 + h * 3 + 2];

    const int beg = g_rowptr[nd];
    const int end = g_rowptr[nd + 1];

    float m_run = -CUDART_INF_F;
    float s_run = 0.f;
    float ax = 0.f, ay = 0.f, az = 0.f, aw = 0.f;

    for (int j = beg; j < end; ++j) {
        const int2 e = g_edge[j];
        const int eid = e.x;
        const int sN = e.y;
        float4 kv = K4[sN * 32 + h * 4 + dsub];
        float d = qv.x * kv.x + qv.y * kv.y + qv.z * kv.z + qv.w * kv.w;
        d += __shfl_xor_sync(0xffffffff, d, 1);
        d += __shfl_xor_sync(0xffffffff, d, 2);   // full 16-dim dot in each quad

        float vw0 = view_w[eid * 3 + 0];
        float vw1 = view_w[eid * 3 + 1];
        float vw2 = view_w[eid * 3 + 2];
        float mix = p0 * vw0 + p1 * vw1 + p2 * vw2;

        float sc = d * 0.25f + __logf(fmaxf(mix, 1e-8f));
        if (!(mix > 0.f)) sc = -1e9f;
        if (dsub == 0) attn_out[(size_t)eid * HH + h] = sc;  // raw score; finalized later

        float nm = fmaxf(m_run, sc);
        float scale = __expf(m_run - nm);
        float p = (sc > -1e8f) ? __expf(sc - nm) : 0.f;
        float4 vv = V4[sN * 32 + h * 4 + dsub];
        s_run = s_run * scale + p;
        ax = ax * scale + p * vv.x;
        ay = ay * scale + p * vv.y;
        az = az * scale + p * vv.z;
        aw = aw * scale + p * vv.w;
        m_run = nm;
    }

    float inv = 1.f / fmaxf(s_run, 1e-8f);
    float4 o = make_float4(ax * inv, ay * inv, az * inv, aw * inv);
    ((float4*)ns_out)[nd * 32 + h * 4 + dsub] = o;
    if (dsub == 0) {
        g_max[nd * HH + h] = m_run;
        g_sum[nd * HH + h] = s_run;
    }
}

// ---------------- finalize attn: one thread per EDGE (8 heads vectorized) ----
__global__ void finalize_attn(const int* __restrict__ dst,
                              float* __restrict__ attn_out, int E) {
    int e = blockIdx.x * blockDim.x + threadIdx.x;
    if (e >= E) return;
    const int d = dst[e];
    float4 sc0 = *(float4*)(attn_out + (size_t)e * HH);
    float4 sc1 = *(float4*)(attn_out + (size_t)e * HH + 4);
    float4 m0 = *(const float4*)(g_max + d * HH);
    float4 m1 = *(const float4*)(g_max + d * HH + 4);
    float4 s0 = *(const float4*)(g_sum + d * HH);
    float4 s1 = *(const float4*)(g_sum + d * HH + 4);

    float4 a0, a1;
    a0.x = (sc0.x > -1e8f) ? __expf(sc0.x - m0.x) / fmaxf(s0.x, 1e-8f) : 0.f;
    a0.y = (sc0.y > -1e8f) ? __expf(sc0.y - m0.y) / fmaxf(s0.y, 1e-8f) : 0.f;
    a0.z = (sc0.z > -1e8f) ? __expf(sc0.z - m0.z) / fmaxf(s0.z, 1e-8f) : 0.f;
    a0.w = (sc0.w > -1e8f) ? __expf(sc0.w - m0.w) / fmaxf(s0.w, 1e-8f) : 0.f;
    a1.x = (sc1.x > -1e8f) ? __expf(sc1.x - m1.x) / fmaxf(s1.x, 1e-8f) : 0.f;
    a1.y = (sc1.y > -1e8f) ? __expf(sc1.y - m1.y) / fmaxf(s1.y, 1e-8f) : 0.f;
    a1.z = (sc1.z > -1e8f) ? __expf(sc1.z - m1.z) / fmaxf(s1.z, 1e-8f) : 0.f;
    a1.w = (sc1.w > -1e8f) ? __expf(sc1.w - m1.w) / fmaxf(s1.w, 1e-8f) : 0.f;

    *(float4*)(attn_out + (size_t)e * HH)     = a0;
    *(float4*)(attn_out + (size_t)e * HH + 4) = a1;
}

// ---------------- launch ------------------------------------------------------
extern "C" void kernel_launch(void* const* d_in, const int* in_sizes, int n_in,
                              void* d_out, int out_size) {
    const float* x   = (const float*)d_in[0];
    const float* pi  = (const float*)d_in[1];
    const float* vw  = (const float*)d_in[2];
    const float* Wq  = (const float*)d_in[3];
    const float* bq  = (const float*)d_in[4];
    const float* Wk  = (const float*)d_in[5];
    const float* bk  = (const float*)d_in[6];
    const float* Wv  = (const float*)d_in[7];
    const float* bv  = (const float*)d_in[8];
    const int*   src = (const int*)d_in[9];
    const int*   dst = (const int*)d_in[10];

    const int n = in_sizes[0] / DD;   // 100000
    const int E = in_sizes[9];        // 1600000

    float* out = (float*)d_out;
    float* ns_out = out;                          // [n, H, DH]
    float* attn_out = out + (size_t)n * DD;       // [E, H]

    cudaFuncSetAttribute(qkv_gemm_tc, cudaFuncAttributeMaxDynamicSharedMemorySize,
                         GEMM_SMEM);

    // 1) QKV projections (3xTF32 tensor core)
    qkv_gemm_tc<<<(n + 127) / 128, 256, GEMM_SMEM>>>(x, Wq, bq, Wk, bk, Wv, bv, n);

    // 2) CSR by dst
    const int nb = (n + 1023) / 1024;
    zero_deg<<<(n + 255) / 256, 256>>>(n);
    hist_kernel<<<(E + 255) / 256, 256>>>(dst, E);
    scan1<<<nb, 1024>>>(n);
    scan3<<<nb, 1024>>>(n, E);
    scatter_kernel<<<(E + 255) / 256, 256>>>(src, dst, E);

    // 3) one warp per node: scores + online softmax + weighted V aggregation
    node_attn<<<(n + 7) / 8, 256>>>(pi, vw, ns_out, attn_out, n);

    // 4) finalize per-edge attention weights
    finalize_attn<<<(E + 255) / 256, 256>>>(dst, attn_out, E);
}

// round 5
// speedup vs baseline: 1.3105x; 1.3105x over previous
#include <cuda_runtime.h>
#include <cuda_fp16.h>
#include <math_constants.h>

// Problem constants (fixed by the dataset)
constexpr int NN = 100000;   // nodes
constexpr int EE = 1600000;  // edges
constexpr int DD = 128;      // model dim
constexpr int HH = 8;        // heads
// DH = 16, M = 3

// ---------------- scratch (static device globals; no allocation) -------------
__device__ float  g_Q[NN * DD];
__device__ __half g_KVh[NN * 256];    // per node: K[128 halfs] then V[128 halfs]
__device__ int   g_deg[NN];
__device__ int   g_rowptr[NN + 1];
__device__ int   g_cursor[NN];
__device__ int2  g_edge[EE];          // (eid, src) packed
__device__ float g_max[NN * HH];
__device__ float g_sum[NN * HH];
__device__ int   g_bsum[128];

// ---------------- f32x2 packed helpers (sm_100+) ------------------------------
typedef unsigned long long ull;

__device__ __forceinline__ void fma2(ull& d, ull a, ull b) {
    asm("fma.rn.f32x2 %0, %1, %2, %0;" : "+l"(d) : "l"(a), "l"(b));
}
__device__ __forceinline__ float2 upk(ull v) {
    float2 r; asm("mov.b64 {%0,%1}, %2;" : "=f"(r.x), "=f"(r.y) : "l"(v)); return r;
}
__device__ __forceinline__ ull swp(ull v) {
    ull r;
    asm("{\n\t.reg .b32 a,b;\n\tmov.b64 {a,b}, %1;\n\tmov.b64 %0, {b,a};\n\t}"
        : "=l"(r) : "l"(v));
    return r;
}

// ---------------- QKV GEMM: C = x @ W + b (f32x2 SIMT, R3-proven) -------------
constexpr int XT = 130;  // transposed-A row stride
constexpr int GEMM_SMEM = (128 * XT + 32 * 128) * 4;

__global__ __launch_bounds__(256) void qkv_gemm(
    const float* __restrict__ x,
    const float* __restrict__ Wq, const float* __restrict__ bq,
    const float* __restrict__ Wk, const float* __restrict__ bk,
    const float* __restrict__ Wv, const float* __restrict__ bv,
    int n)
{
    extern __shared__ float smem[];
    float* xs_t = smem;                   // [128 k][XT rows]
    float* ws   = smem + 128 * XT;        // [32 k][128 cols]

    const int tid = threadIdx.x;
    const int tx = tid & 15;
    const int ty = tid >> 4;
    const int row0 = blockIdx.x * 128;

    for (int i = tid; i < 128 * 32; i += 256) {
        int r = i >> 5, c = (i & 31) << 2;
        float4 v = make_float4(0.f, 0.f, 0.f, 0.f);
        if (row0 + r < n) v = *(const float4*)(x + (size_t)(row0 + r) * DD + c);
        xs_t[(c + 0) * XT + r] = v.x;
        xs_t[(c + 1) * XT + r] = v.y;
        xs_t[(c + 2) * XT + r] = v.z;
        xs_t[(c + 3) * XT + r] = v.w;
    }

    const float* Ws[3] = {Wq, Wk, Wv};
    const float* Bs[3] = {bq, bk, bv};

    const int ra = ty * 4;
    const int ca = tx * 4;

    for (int w = 0; w < 3; ++w) {
        ull accD[4][4], accX[4][4];
#pragma unroll
        for (int i = 0; i < 4; ++i)
#pragma unroll
            for (int j = 0; j < 4; ++j) { accD[i][j] = 0ull; accX[i][j] = 0ull; }

        const float* W = Ws[w];
        for (int kb = 0; kb < 4; ++kb) {
            __syncthreads();
            for (int i = tid; i < 32 * 32; i += 256) {
                int r = i >> 5, c = (i & 31) << 2;
                *(float4*)(&ws[r * 128 + c]) =
                    *(const float4*)(W + (size_t)(kb * 32 + r) * DD + c);
            }
            __syncthreads();
#pragma unroll
            for (int kk = 0; kk < 32; ++kk) {
                const float* arow = xs_t + (kb * 32 + kk) * XT;  // GLOBAL k
                ull aP[4];
                aP[0] = *(const ull*)(arow + ra);
                aP[1] = *(const ull*)(arow + ra + 2);
                aP[2] = *(const ull*)(arow + 64 + ra);
                aP[3] = *(const ull*)(arow + 64 + ra + 2);

                const float* brow = ws + kk * 128;
                ulonglong2 bl = *(const ulonglong2*)(brow + ca);
                ulonglong2 bh = *(const ulonglong2*)(brow + 64 + ca);
                ull bP[4] = {bl.x, bl.y, bh.x, bh.y};
                ull bS[4] = {swp(bl.x), swp(bl.y), swp(bh.x), swp(bh.y)};

#pragma unroll
                for (int i = 0; i < 4; ++i)
#pragma unroll
                    for (int j = 0; j < 4; ++j) {
                        fma2(accD[i][j], aP[i], bP[j]);
                        fma2(accX[i][j], aP[i], bS[j]);
                    }
            }
        }

        float vals[8][8];
#pragma unroll
        for (int i2 = 0; i2 < 4; ++i2)
#pragma unroll
            for (int j2 = 0; j2 < 4; ++j2) {
                float2 d = upk(accD[i2][j2]);
                float2 s = upk(accX[i2][j2]);
                vals[2 * i2][2 * j2]         = d.x;
                vals[2 * i2 + 1][2 * j2 + 1] = d.y;
                vals[2 * i2][2 * j2 + 1]     = s.x;
                vals[2 * i2 + 1][2 * j2]     = s.y;
            }

        float4 bb0 = *(const float4*)(Bs[w] + ca);
        float4 bb1 = *(const float4*)(Bs[w] + 64 + ca);
#pragma unroll
        for (int i = 0; i < 8; ++i) {
            int r = row0 + ((i < 4) ? (ra + i) : (64 + ra + (i - 4)));
            if (r >= n) continue;
            float o[8];
            o[0] = vals[i][0] + bb0.x; o[1] = vals[i][1] + bb0.y;
            o[2] = vals[i][2] + bb0.z; o[3] = vals[i][3] + bb0.w;
            o[4] = vals[i][4] + bb1.x; o[5] = vals[i][5] + bb1.y;
            o[6] = vals[i][6] + bb1.z; o[7] = vals[i][7] + bb1.w;
            if (w == 0) {
                *(float4*)(g_Q + (size_t)r * DD + ca) =
                    make_float4(o[0], o[1], o[2], o[3]);
                *(float4*)(g_Q + (size_t)r * DD + 64 + ca) =
                    make_float4(o[4], o[5], o[6], o[7]);
            } else {
                // K at half-offset 0, V at 128, within the node's 256-half row
                __half* dst = g_KVh + (size_t)r * 256 + (w == 1 ? 0 : 128);
                *(__half2*)(dst + ca)          = __floats2half2_rn(o[0], o[1]);
                *(__half2*)(dst + ca + 2)      = __floats2half2_rn(o[2], o[3]);
                *(__half2*)(dst + 64 + ca)     = __floats2half2_rn(o[4], o[5]);
                *(__half2*)(dst + 64 + ca + 2) = __floats2half2_rn(o[6], o[7]);
            }
        }
    }
}

// ---------------- CSR construction -------------------------------------------
__global__ void zero_deg(int n) {
    int i = blockIdx.x * blockDim.x + threadIdx.x;
    if (i < n) g_deg[i] = 0;
}

__global__ void hist_kernel(const int* __restrict__ dst, int E) {
    int i = blockIdx.x * blockDim.x + threadIdx.x;
    if (i < E) atomicAdd(&g_deg[dst[i]], 1);
}

__global__ __launch_bounds__(1024) void scan1(int n) {
    __shared__ int sm[1024];
    const int t = threadIdx.x;
    const int i = blockIdx.x * 1024 + t;
    int v = (i < n) ? g_deg[i] : 0;
    sm[t] = v;
    __syncthreads();
    for (int off = 1; off < 1024; off <<= 1) {
        int u = (t >= off) ? sm[t - off] : 0;
        __syncthreads();
        sm[t] += u;
        __syncthreads();
    }
    if (i < n) g_rowptr[i] = sm[t] - v;
    if (t == 1023) g_bsum[blockIdx.x] = sm[t];
}

__global__ __launch_bounds__(1024) void scan3(int n, int E) {
    __shared__ int soff;
    const int t = threadIdx.x;
    if (t == 0) soff = 0;
    __syncthreads();
    int acc = 0;
    for (int j = t; j < blockIdx.x; j += 1024) acc += g_bsum[j];
    if (acc) atomicAdd(&soff, acc);
    __syncthreads();
    const int i = blockIdx.x * 1024 + t;
    if (i < n) {
        int r = g_rowptr[i] + soff;
        g_rowptr[i] = r;
        g_cursor[i] = r;
    }
    if (i == 0) g_rowptr[n] = E;
}

__global__ void scatter_kernel(const int* __restrict__ src,
                               const int* __restrict__ dst, int E) {
    int i = blockIdx.x * blockDim.x + threadIdx.x;
    if (i < E) {
        int p = atomicAdd(&g_cursor[dst[i]], 1);
        g_edge[p] = make_int2(i, src[i]);
    }
}

// ---------------- per-node online-softmax attention --------------------------
// One warp per node. lane -> (head = lane/4, dim-quad = lane%4).
// K/V stored fp16 interleaved: 512B per node total (one warp-wide uint2 each).
__global__ __launch_bounds__(256) void node_attn(
    const float* __restrict__ pi, const float* __restrict__ view_w,
    float* __restrict__ ns_out, float* __restrict__ attn_out, int n)
{
    int warp = (blockIdx.x * blockDim.x + threadIdx.x) >> 5;
    if (warp >= n) return;
    const int lane = threadIdx.x & 31;
    const int h = lane >> 2;
    const int nd = warp;
    const int dsub = lane & 3;

    const float4* Q4 = (const float4*)g_Q;
    const uint2* KVu = (const uint2*)g_KVh;   // 64 uint2 per node (512B)

    const float4 qv = Q4[nd * 32 + lane];     // lane = h*4+dsub ✓
    const float p0 = pi[nd * 24 + h * 3 + 0];
    const float p1 = pi[nd * 24 + h * 3 + 1];
    const float p2 = pi[nd * 24 + h * 3 + 2];

    const int beg = g_rowptr[nd];
    const int end = g_rowptr[nd + 1];

    float m_run = -CUDART_INF_F;
    float s_run = 0.f;
    float ax = 0.f, ay = 0.f, az = 0.f, aw = 0.f;

    for (int j = beg; j < end; ++j) {
        const int2 e = g_edge[j];
        const int eid = e.x;
        const int sN = e.y;

        uint2 ku = KVu[(size_t)sN * 64 + lane];       // 4 K halfs
        uint2 vu = KVu[(size_t)sN * 64 + 32 + lane];  // 4 V halfs
        float2 k01 = __half22float2(*(__half2*)&ku.x);
        float2 k23 = __half22float2(*(__half2*)&ku.y);

        float d = qv.x * k01.x + qv.y * k01.y + qv.z * k23.x + qv.w * k23.y;
        d += __shfl_xor_sync(0xffffffff, d, 1);
        d += __shfl_xor_sync(0xffffffff, d, 2);   // full 16-dim dot per quad

        float vw0 = view_w[eid * 3 + 0];
        float vw1 = view_w[eid * 3 + 1];
        float vw2 = view_w[eid * 3 + 2];
        float mix = p0 * vw0 + p1 * vw1 + p2 * vw2;

        float sc = d * 0.25f + __logf(fmaxf(mix, 1e-8f));
        if (!(mix > 0.f)) sc = -1e9f;
        if (dsub == 0) attn_out[(size_t)eid * HH + h] = sc;

        float nm = fmaxf(m_run, sc);
        float scale = __expf(m_run - nm);
        float p = (sc > -1e8f) ? __expf(sc - nm) : 0.f;
        float2 v01 = __half22float2(*(__half2*)&vu.x);
        float2 v23 = __half22float2(*(__half2*)&vu.y);
        s_run = s_run * scale + p;
        ax = ax * scale + p * v01.x;
        ay = ay * scale + p * v01.y;
        az = az * scale + p * v23.x;
        aw = aw * scale + p * v23.y;
        m_run = nm;
    }

    float inv = 1.f / fmaxf(s_run, 1e-8f);
    ((float4*)ns_out)[nd * 32 + lane] = make_float4(ax * inv, ay * inv,
                                                    az * inv, aw * inv);
    if (dsub == 0) {
        g_max[nd * HH + h] = m_run;
        g_sum[nd * HH + h] = s_run;
    }
}

// ---------------- finalize attn: one thread per EDGE (8 heads vectorized) ----
__global__ void finalize_attn(const int* __restrict__ dst,
                              float* __restrict__ attn_out, int E) {
    int e = blockIdx.x * blockDim.x + threadIdx.x;
    if (e >= E) return;
    const int d = dst[e];
    float4 sc0 = *(float4*)(attn_out + (size_t)e * HH);
    float4 sc1 = *(float4*)(attn_out + (size_t)e * HH + 4);
    float4 m0 = *(const float4*)(g_max + d * HH);
    float4 m1 = *(const float4*)(g_max + d * HH + 4);
    float4 s0 = *(const float4*)(g_sum + d * HH);
    float4 s1 = *(const float4*)(g_sum + d * HH + 4);

    float4 a0, a1;
    a0.x = (sc0.x > -1e8f) ? __expf(sc0.x - m0.x) / fmaxf(s0.x, 1e-8f) : 0.f;
    a0.y = (sc0.y > -1e8f) ? __expf(sc0.y - m0.y) / fmaxf(s0.y, 1e-8f) : 0.f;
    a0.z = (sc0.z > -1e8f) ? __expf(sc0.z - m0.z) / fmaxf(s0.z, 1e-8f) : 0.f;
    a0.w = (sc0.w > -1e8f) ? __expf(sc0.w - m0.w) / fmaxf(s0.w, 1e-8f) : 0.f;
    a1.x = (sc1.x > -1e8f) ? __expf(sc1.x - m1.x) / fmaxf(s1.x, 1e-8f) : 0.f;
    a1.y = (sc1.y > -1e8f) ? __expf(sc1.y - m1.y) / fmaxf(s1.y, 1e-8f) : 0.f;
    a1.z = (sc1.z > -1e8f) ? __expf(sc1.z - m1.z) / fmaxf(s1.z, 1e-8f) : 0.f;
    a1.w = (sc1.w > -1e8f) ? __expf(sc1.w - m1.w) / fmaxf(s1.w, 1e-8f) : 0.f;

    *(float4*)(attn_out + (size_t)e * HH)     = a0;
    *(float4*)(attn_out + (size_t)e * HH + 4) = a1;
}

// ---------------- launch ------------------------------------------------------
extern "C" void kernel_launch(void* const* d_in, const int* in_sizes, int n_in,
                              void* d_out, int out_size) {
    const float* x   = (const float*)d_in[0];
    const float* pi  = (const float*)d_in[1];
    const float* vw  = (const float*)d_in[2];
    const float* Wq  = (const float*)d_in[3];
    const float* bq  = (const float*)d_in[4];
    const float* Wk  = (const float*)d_in[5];
    const float* bk  = (const float*)d_in[6];
    const float* Wv  = (const float*)d_in[7];
    const float* bv  = (const float*)d_in[8];
    const int*   src = (const int*)d_in[9];
    const int*   dst = (const int*)d_in[10];

    const int n = in_sizes[0] / DD;   // 100000
    const int E = in_sizes[9];        // 1600000

    float* out = (float*)d_out;
    float* ns_out = out;                          // [n, H, DH]
    float* attn_out = out + (size_t)n * DD;       // [E, H]

    cudaFuncSetAttribute(qkv_gemm, cudaFuncAttributeMaxDynamicSharedMemorySize,
                         GEMM_SMEM);

    const int nb = (n + 1023) / 1024;
    // Order chosen so qkv_gemm is the 4th launch -> captured by ncu next round.
    zero_deg<<<(n + 255) / 256, 256>>>(n);
    hist_kernel<<<(E + 255) / 256, 256>>>(dst, E);
    scan1<<<nb, 1024>>>(n);
    qkv_gemm<<<(n + 127) / 128, 256, GEMM_SMEM>>>(x, Wq, bq, Wk, bk, Wv, bv, n);
    scan3<<<nb, 1024>>>(n, E);
    scatter_kernel<<<(E + 255) / 256, 256>>>(src, dst, E);

    node_attn<<<(n + 7) / 8, 256>>>(pi, vw, ns_out, attn_out, n);
    finalize_attn<<<(E + 255) / 256, 256>>>(dst, attn_out, E);
}

// round 6
// speedup vs baseline: 1.6035x; 1.2236x over previous
#include <cuda_runtime.h>
#include <cuda_fp16.h>
#include <math_constants.h>

// Problem constants (fixed by the dataset)
constexpr int NN = 100000;   // nodes
constexpr int EE = 1600000;  // edges
constexpr int DD = 128;      // model dim
constexpr int HH = 8;        // heads
// DH = 16, M = 3

// ---------------- scratch (static device globals; no allocation) -------------
__device__ float  g_Q[NN * DD];
__device__ __half g_KVh[NN * 256];    // per node: K[128 halfs] then V[128 halfs]
__device__ int   g_deg[NN];
__device__ int   g_rowptr[NN + 1];
__device__ int   g_cursor[NN];
__device__ int2  g_edge[EE];          // (eid, src) packed
__device__ float g_max[NN * HH];
__device__ float g_sum[NN * HH];
__device__ int   g_bsum[128];

// ---------------- TF32 helpers ------------------------------------------------
__device__ __forceinline__ float to_tf32(float a) {
    float r; asm("cvt.rna.tf32.f32 %0, %1;" : "=f"(r) : "f"(a)); return r;
}

__device__ __forceinline__ void mma_tf32(float c[4], const unsigned a[4],
                                         const unsigned b[2]) {
    asm volatile(
        "mma.sync.aligned.m16n8k8.row.col.f32.tf32.tf32.f32 "
        "{%0,%1,%2,%3}, {%4,%5,%6,%7}, {%8,%9}, {%0,%1,%2,%3};"
        : "+f"(c[0]), "+f"(c[1]), "+f"(c[2]), "+f"(c[3])
        : "r"(a[0]), "r"(a[1]), "r"(a[2]), "r"(a[3]), "r"(b[0]), "r"(b[1]));
}

// ---------------- QKV GEMM (tensor core, single-pass TF32) --------------------
// Block tile 128x128. x tile (tf32-converted) fully K-resident; W chunked in
// 64-k slabs so smem = 102.4 KB -> 2 CTAs/SM. 8 warps: 4(M) x 2(N), warp tile
// 32x64 = 2 m-tiles x 8 n-tiles of m16n8k8. Conversion hoisted to smem fill.
constexpr int XS = 132;   // xs row stride  (A-frag loads conflict-free)
constexpr int WS = 136;   // ws row stride  (B-frag loads conflict-free)
constexpr int GEMM_SMEM = (128 * XS + 64 * WS) * 4;   // 102400 B

__global__ __launch_bounds__(256, 2) void qkv_gemm_tc(
    const float* __restrict__ x,
    const float* __restrict__ Wq, const float* __restrict__ bq,
    const float* __restrict__ Wk, const float* __restrict__ bk,
    const float* __restrict__ Wv, const float* __restrict__ bv,
    int n)
{
    extern __shared__ float smem[];
    float* xs = smem;               // [128 rows][XS]  tf32 values
    float* ws = smem + 128 * XS;    // [64 k][WS]      tf32 values (one chunk)

    const int tid  = threadIdx.x;
    const int lane = tid & 31;
    const int wid  = tid >> 5;
    const int warpM = wid & 3;      // 32 rows each
    const int warpN = wid >> 2;     // 64 cols each
    const int row0 = blockIdx.x * 128;

    // load + convert x tile [128][128]; OOB rows -> 0
    for (int i = tid; i < 128 * 32; i += 256) {
        int r = i >> 5, c = (i & 31) << 2;
        float4 v = make_float4(0.f, 0.f, 0.f, 0.f);
        if (row0 + r < n) v = *(const float4*)(x + (size_t)(row0 + r) * DD + c);
        xs[r * XS + c]     = to_tf32(v.x);
        xs[r * XS + c + 1] = to_tf32(v.y);
        xs[r * XS + c + 2] = to_tf32(v.z);
        xs[r * XS + c + 3] = to_tf32(v.w);
    }

    const float* Ws[3] = {Wq, Wk, Wv};
    const float* Bs[3] = {bq, bk, bv};

    const int gidx = lane >> 2;     // 0..7
    const int tidx = lane & 3;      // 0..3

    for (int w = 0; w < 3; ++w) {
        float C[2][8][4];
#pragma unroll
        for (int mt = 0; mt < 2; ++mt)
#pragma unroll
            for (int nt = 0; nt < 8; ++nt)
#pragma unroll
                for (int q = 0; q < 4; ++q) C[mt][nt][q] = 0.f;

        for (int chunk = 0; chunk < 2; ++chunk) {
            __syncthreads();
            // load + convert W k-slab [64][128]
            for (int i = tid; i < 64 * 32; i += 256) {
                int kr = i >> 5, c = (i & 31) << 2;
                float4 v = *(const float4*)(Ws[w] + (size_t)(chunk * 64 + kr) * DD + c);
                ws[kr * WS + c]     = to_tf32(v.x);
                ws[kr * WS + c + 1] = to_tf32(v.y);
                ws[kr * WS + c + 2] = to_tf32(v.z);
                ws[kr * WS + c + 3] = to_tf32(v.w);
            }
            __syncthreads();

#pragma unroll
            for (int k8 = 0; k8 < 8; ++k8) {
                const int kb = k8 * 8;
                unsigned a[2][4];
#pragma unroll
                for (int mt = 0; mt < 2; ++mt) {
                    int row = warpM * 32 + mt * 16 + gidx;
                    int col = chunk * 64 + kb + tidx;
                    a[mt][0] = __float_as_uint(xs[row * XS + col]);
                    a[mt][1] = __float_as_uint(xs[(row + 8) * XS + col]);
                    a[mt][2] = __float_as_uint(xs[row * XS + col + 4]);
                    a[mt][3] = __float_as_uint(xs[(row + 8) * XS + col + 4]);
                }
#pragma unroll
                for (int nt = 0; nt < 8; ++nt) {
                    int colb = warpN * 64 + nt * 8 + gidx;
                    int krow = kb + tidx;
                    unsigned b[2];
                    b[0] = __float_as_uint(ws[krow * WS + colb]);
                    b[1] = __float_as_uint(ws[(krow + 4) * WS + colb]);
                    mma_tf32(C[0][nt], a[0], b);
                    mma_tf32(C[1][nt], a[1], b);
                }
            }
        }

        // epilogue: bias add + store. Q fp32; K/V fp16 into g_KVh.
        const float* B = Bs[w];
#pragma unroll
        for (int nt = 0; nt < 8; ++nt) {
            int col = warpN * 64 + nt * 8 + 2 * tidx;
            float b0 = __ldg(B + col);
            float b1 = __ldg(B + col + 1);
#pragma unroll
            for (int mt = 0; mt < 2; ++mt) {
                int r0 = row0 + warpM * 32 + mt * 16 + gidx;
                int r1 = r0 + 8;
                float o00 = C[mt][nt][0] + b0, o01 = C[mt][nt][1] + b1;
                float o10 = C[mt][nt][2] + b0, o11 = C[mt][nt][3] + b1;
                if (w == 0) {
                    if (r0 < n) *(float2*)(g_Q + (size_t)r0 * DD + col) =
                        make_float2(o00, o01);
                    if (r1 < n) *(float2*)(g_Q + (size_t)r1 * DD + col) =
                        make_float2(o10, o11);
                } else {
                    int off = (w == 1) ? 0 : 128;
                    if (r0 < n) *(__half2*)(g_KVh + (size_t)r0 * 256 + off + col) =
                        __floats2half2_rn(o00, o01);
                    if (r1 < n) *(__half2*)(g_KVh + (size_t)r1 * 256 + off + col) =
                        __floats2half2_rn(o10, o11);
                }
            }
        }
    }
}

// ---------------- CSR construction -------------------------------------------
__global__ void hist_kernel(const int* __restrict__ dst, int E) {
    int i = blockIdx.x * blockDim.x + threadIdx.x;
    if (i < E) atomicAdd(&g_deg[dst[i]], 1);
}

// block-local exclusive scan; also zeroes g_deg for the next replay
__global__ __launch_bounds__(1024) void scan1(int n) {
    __shared__ int sm[1024];
    const int t = threadIdx.x;
    const int i = blockIdx.x * 1024 + t;
    int v = (i < n) ? g_deg[i] : 0;
    if (i < n) g_deg[i] = 0;            // ready for next launch (graph replay)
    sm[t] = v;
    __syncthreads();
    for (int off = 1; off < 1024; off <<= 1) {
        int u = (t >= off) ? sm[t - off] : 0;
        __syncthreads();
        sm[t] += u;
        __syncthreads();
    }
    if (i < n) g_rowptr[i] = sm[t] - v;
    if (t == 1023) g_bsum[blockIdx.x] = sm[t];
}

__global__ __launch_bounds__(1024) void scan3(int n, int E) {
    __shared__ int soff;
    const int t = threadIdx.x;
    if (t == 0) soff = 0;
    __syncthreads();
    int acc = 0;
    for (int j = t; j < blockIdx.x; j += 1024) acc += g_bsum[j];
    if (acc) atomicAdd(&soff, acc);
    __syncthreads();
    const int i = blockIdx.x * 1024 + t;
    if (i < n) {
        int r = g_rowptr[i] + soff;
        g_rowptr[i] = r;
        g_cursor[i] = r;
    }
    if (i == 0) g_rowptr[n] = E;
}

__global__ void scatter_kernel(const int* __restrict__ src,
                               const int* __restrict__ dst, int E) {
    int i = blockIdx.x * blockDim.x + threadIdx.x;
    if (i < E) {
        int p = atomicAdd(&g_cursor[dst[i]], 1);
        g_edge[p] = make_int2(i, src[i]);
    }
}

// ---------------- per-node online-softmax attention --------------------------
// One warp per node. lane -> (head = lane/4, dim-quad = lane%4).
__global__ __launch_bounds__(256) void node_attn(
    const float* __restrict__ pi, const float* __restrict__ view_w,
    float* __restrict__ ns_out, float* __restrict__ attn_out, int n)
{
    int warp = (blockIdx.x * blockDim.x + threadIdx.x) >> 5;
    if (warp >= n) return;
    const int lane = threadIdx.x & 31;
    const int h = lane >> 2;
    const int nd = warp;
    const int dsub = lane & 3;

    const float4* Q4 = (const float4*)g_Q;
    const uint2* KVu = (const uint2*)g_KVh;   // 64 uint2 per node (512B)

    const float4 qv = Q4[nd * 32 + lane];
    const float p0 = pi[nd * 24 + h * 3 + 0];
    const float p1 = pi[nd * 24 + h * 3 + 1];
    const float p2 = pi[nd * 24 + h * 3 + 2];

    const int beg = g_rowptr[nd];
    const int end = g_rowptr[nd + 1];

    float m_run = -CUDART_INF_F;
    float s_run = 0.f;
    float ax = 0.f, ay = 0.f, az = 0.f, aw = 0.f;

    for (int j = beg; j < end; ++j) {
        const int2 e = g_edge[j];
        const int eid = e.x;
        const int sN = e.y;

        uint2 ku = KVu[(size_t)sN * 64 + lane];
        uint2 vu = KVu[(size_t)sN * 64 + 32 + lane];
        float2 k01 = __half22float2(*(__half2*)&ku.x);
        float2 k23 = __half22float2(*(__half2*)&ku.y);

        float d = qv.x * k01.x + qv.y * k01.y + qv.z * k23.x + qv.w * k23.y;
        d += __shfl_xor_sync(0xffffffff, d, 1);
        d += __shfl_xor_sync(0xffffffff, d, 2);

        float vw0 = view_w[eid * 3 + 0];
        float vw1 = view_w[eid * 3 + 1];
        float vw2 = view_w[eid * 3 + 2];
        float mix = p0 * vw0 + p1 * vw1 + p2 * vw2;

        float sc = d * 0.25f + __logf(fmaxf(mix, 1e-8f));
        if (!(mix > 0.f)) sc = -1e9f;
        if (dsub == 0) attn_out[(size_t)eid * HH + h] = sc;

        float nm = fmaxf(m_run, sc);
        float scale = __expf(m_run - nm);
        float p = (sc > -1e8f) ? __expf(sc - nm) : 0.f;
        float2 v01 = __half22float2(*(__half2*)&vu.x);
        float2 v23 = __half22float2(*(__half2*)&vu.y);
        s_run = s_run * scale + p;
        ax = ax * scale + p * v01.x;
        ay = ay * scale + p * v01.y;
        az = az * scale + p * v23.x;
        aw = aw * scale + p * v23.y;
        m_run = nm;
    }

    float inv = 1.f / fmaxf(s_run, 1e-8f);
    ((float4*)ns_out)[nd * 32 + lane] = make_float4(ax * inv, ay * inv,
                                                    az * inv, aw * inv);
    if (dsub == 0) {
        g_max[nd * HH + h] = m_run;
        g_sum[nd * HH + h] = s_run;
    }
}

// ---------------- finalize attn: one thread per EDGE (8 heads vectorized) ----
__global__ void finalize_attn(const int* __restrict__ dst,
                              float* __restrict__ attn_out, int E) {
    int e = blockIdx.x * blockDim.x + threadIdx.x;
    if (e >= E) return;
    const int d = dst[e];
    float4 sc0 = *(float4*)(attn_out + (size_t)e * HH);
    float4 sc1 = *(float4*)(attn_out + (size_t)e * HH + 4);
    float4 m0 = *(const float4*)(g_max + d * HH);
    float4 m1 = *(const float4*)(g_max + d * HH + 4);
    float4 s0 = *(const float4*)(g_sum + d * HH);
    float4 s1 = *(const float4*)(g_sum + d * HH + 4);

    float4 a0, a1;
    a0.x = (sc0.x > -1e8f) ? __expf(sc0.x - m0.x) / fmaxf(s0.x, 1e-8f) : 0.f;
    a0.y = (sc0.y > -1e8f) ? __expf(sc0.y - m0.y) / fmaxf(s0.y, 1e-8f) : 0.f;
    a0.z = (sc0.z > -1e8f) ? __expf(sc0.z - m0.z) / fmaxf(s0.z, 1e-8f) : 0.f;
    a0.w = (sc0.w > -1e8f) ? __expf(sc0.w - m0.w) / fmaxf(s0.w, 1e-8f) : 0.f;
    a1.x = (sc1.x > -1e8f) ? __expf(sc1.x - m1.x) / fmaxf(s1.x, 1e-8f) : 0.f;
    a1.y = (sc1.y > -1e8f) ? __expf(sc1.y - m1.y) / fmaxf(s1.y, 1e-8f) : 0.f;
    a1.z = (sc1.z > -1e8f) ? __expf(sc1.z - m1.z) / fmaxf(s1.z, 1e-8f) : 0.f;
    a1.w = (sc1.w > -1e8f) ? __expf(sc1.w - m1.w) / fmaxf(s1.w, 1e-8f) : 0.f;

    *(float4*)(attn_out + (size_t)e * HH)     = a0;
    *(float4*)(attn_out + (size_t)e * HH + 4) = a1;
}

// ---------------- launch ------------------------------------------------------
extern "C" void kernel_launch(void* const* d_in, const int* in_sizes, int n_in,
                              void* d_out, int out_size) {
    const float* x   = (const float*)d_in[0];
    const float* pi  = (const float*)d_in[1];
    const float* vw  = (const float*)d_in[2];
    const float* Wq  = (const float*)d_in[3];
    const float* bq  = (const float*)d_in[4];
    const float* Wk  = (const float*)d_in[5];
    const float* bk  = (const float*)d_in[6];
    const float* Wv  = (const float*)d_in[7];
    const float* bv  = (const float*)d_in[8];
    const int*   src = (const int*)d_in[9];
    const int*   dst = (const int*)d_in[10];

    const int n = in_sizes[0] / DD;   // 100000
    const int E = in_sizes[9];        // 1600000

    float* out = (float*)d_out;
    float* ns_out = out;                          // [n, H, DH]
    float* attn_out = out + (size_t)n * DD;       // [E, H]

    cudaFuncSetAttribute(qkv_gemm_tc, cudaFuncAttributeMaxDynamicSharedMemorySize,
                         GEMM_SMEM);

    const int nb = (n + 1023) / 1024;
    // g_deg starts zeroed (static init) and is re-zeroed by scan1 each replay.
    hist_kernel<<<(E + 255) / 256, 256>>>(dst, E);
    scan1<<<nb, 1024>>>(n);
    scan3<<<nb, 1024>>>(n, E);
    qkv_gemm_tc<<<(n + 127) / 128, 256, GEMM_SMEM>>>(x, Wq, bq, Wk, bk, Wv, bv, n);  // 4th: profiled
    scatter_kernel<<<(E + 255) / 256, 256>>>(src, dst, E);

    node_attn<<<(n + 7) / 8, 256>>>(pi, vw, ns_out, attn_out, n);
    finalize_attn<<<(E + 255) / 256, 256>>>(dst, attn_out, E);
}

// round 7
// speedup vs baseline: 1.9026x; 1.1865x over previous
#include <cuda_runtime.h>
#include <cuda_fp16.h>
#include <math_constants.h>

// Problem constants (fixed by the dataset)
constexpr int NN = 100000;   // nodes
constexpr int EE = 1600000;  // edges
constexpr int DD = 128;      // model dim
constexpr int HH = 8;        // heads
// DH = 16, M = 3

// ---------------- scratch (static device globals; no allocation) -------------
__device__ float  g_Q[NN * DD];
__device__ __half g_KVh[NN * 256];    // per node: K[128 halfs] then V[128 halfs]
__device__ int    g_deg[NN];
__device__ int    g_rowptr[NN + 1];
__device__ int    g_cursor[NN];
__device__ int2   g_edge[EE];         // (eid, src) packed
__device__ float  g_scores[(size_t)EE * HH];  // raw scores in CSR order
__device__ int    g_bsum[128];

// ---------------- TF32 helpers ------------------------------------------------
__device__ __forceinline__ float to_tf32(float a) {
    float r; asm("cvt.rna.tf32.f32 %0, %1;" : "=f"(r) : "f"(a)); return r;
}

__device__ __forceinline__ void mma_tf32(float c[4], const unsigned a[4],
                                         const unsigned b[2]) {
    asm volatile(
        "mma.sync.aligned.m16n8k8.row.col.f32.tf32.tf32.f32 "
        "{%0,%1,%2,%3}, {%4,%5,%6,%7}, {%8,%9}, {%0,%1,%2,%3};"
        : "+f"(c[0]), "+f"(c[1]), "+f"(c[2]), "+f"(c[3])
        : "r"(a[0]), "r"(a[1]), "r"(a[2]), "r"(a[3]), "r"(b[0]), "r"(b[1]));
}

// ---------------- QKV GEMM (TF32 tensor core, cp.async W pipeline) ------------
// A (x tile, tf32) fully K-resident. W streamed as 12 k-slabs (3 W x 4 slabs of
// 32 k), double-buffered via cp.async.cg; each slab converted to tf32 in place.
// 8 warps: 4(M) x 2(N); warp tile 32x64 = 2 m-tiles x 8 n-tiles of m16n8k8.
constexpr int XS = 132;            // xs row stride
constexpr int WSS = 136;           // W slab row stride
constexpr int SLABF = 32 * WSS;    // floats per slab buffer
constexpr int GEMM_SMEM = (128 * XS + 2 * SLABF) * 4;   // 102400 B

__device__ __forceinline__ void cpasync_w_slab(const float* Wsrc, float* buf,
                                               int tid) {
    unsigned sb = (unsigned)__cvta_generic_to_shared(buf);
#pragma unroll
    for (int i = 0; i < 4; ++i) {
        int idx = tid + i * 256;
        int kr = idx >> 5, c = (idx & 31) << 2;
        unsigned sa = sb + (unsigned)((kr * WSS + c) * 4);
        asm volatile("cp.async.cg.shared.global [%0], [%1], 16;\n"
                     :: "r"(sa), "l"(Wsrc + (size_t)kr * DD + c));
    }
}

__global__ __launch_bounds__(256, 2) void qkv_gemm_tc(
    const float* __restrict__ x,
    const float* __restrict__ Wq, const float* __restrict__ bq,
    const float* __restrict__ Wk, const float* __restrict__ bk,
    const float* __restrict__ Wv, const float* __restrict__ bv,
    int n)
{
    extern __shared__ float smem[];
    float* xs  = smem;               // [128 rows][XS]  tf32 values
    float* wsb = smem + 128 * XS;    // [2][32 k][WSS]  W slab double buffer

    const int tid  = threadIdx.x;
    const int lane = tid & 31;
    const int wid  = tid >> 5;
    const int warpM = wid & 3;
    const int warpN = wid >> 2;
    const int row0 = blockIdx.x * 128;

    // load + convert x tile [128][128]; OOB rows -> 0
    for (int i = tid; i < 128 * 32; i += 256) {
        int r = i >> 5, c = (i & 31) << 2;
        float4 v = make_float4(0.f, 0.f, 0.f, 0.f);
        if (row0 + r < n) v = *(const float4*)(x + (size_t)(row0 + r) * DD + c);
        xs[r * XS + c]     = to_tf32(v.x);
        xs[r * XS + c + 1] = to_tf32(v.y);
        xs[r * XS + c + 2] = to_tf32(v.z);
        xs[r * XS + c + 3] = to_tf32(v.w);
    }

    const float* Ws[3] = {Wq, Wk, Wv};
    const float* Bs[3] = {bq, bk, bv};

    const int gidx = lane >> 2;     // 0..7
    const int tidx = lane & 3;      // 0..3

    // prologue: slab 0 in flight
    cpasync_w_slab(Ws[0], wsb, tid);
    asm volatile("cp.async.commit_group;\n");

    float C[2][8][4];

#pragma unroll 1
    for (int ls = 0; ls < 12; ++ls) {
        const int w = ls >> 2;      // which W
        const int s = ls & 3;       // k-slab within W

        if (s == 0) {
#pragma unroll
            for (int mt = 0; mt < 2; ++mt)
#pragma unroll
                for (int nt = 0; nt < 8; ++nt)
#pragma unroll
                    for (int q = 0; q < 4; ++q) C[mt][nt][q] = 0.f;
        }

        asm volatile("cp.async.wait_group 0;\n");
        __syncthreads();   // slab ls arrived; everyone done with prev compute

        if (ls < 11) {
            const int nls = ls + 1;
            cpasync_w_slab(Ws[nls >> 2] + (size_t)((nls & 3) * 32) * DD,
                           wsb + (nls & 1) * SLABF, tid);
            asm volatile("cp.async.commit_group;\n");
        }

        float* wb = wsb + (ls & 1) * SLABF;
        // convert slab to tf32 in place
#pragma unroll
        for (int i = 0; i < 4; ++i) {
            int idx = tid + i * 256;
            int kr = idx >> 5, c = (idx & 31) << 2;
            float4* p = (float4*)(wb + kr * WSS + c);
            float4 v = *p;
            v.x = to_tf32(v.x); v.y = to_tf32(v.y);
            v.z = to_tf32(v.z); v.w = to_tf32(v.w);
            *p = v;
        }
        __syncthreads();

#pragma unroll
        for (int k8 = 0; k8 < 4; ++k8) {
            unsigned a[2][4];
#pragma unroll
            for (int mt = 0; mt < 2; ++mt) {
                int row = warpM * 32 + mt * 16 + gidx;
                int col = s * 32 + k8 * 8 + tidx;
                a[mt][0] = __float_as_uint(xs[row * XS + col]);
                a[mt][1] = __float_as_uint(xs[(row + 8) * XS + col]);
                a[mt][2] = __float_as_uint(xs[row * XS + col + 4]);
                a[mt][3] = __float_as_uint(xs[(row + 8) * XS + col + 4]);
            }
#pragma unroll
            for (int nt = 0; nt < 8; ++nt) {
                int colb = warpN * 64 + nt * 8 + gidx;
                int krow = k8 * 8 + tidx;
                unsigned b[2];
                b[0] = __float_as_uint(wb[krow * WSS + colb]);
                b[1] = __float_as_uint(wb[(krow + 4) * WSS + colb]);
                mma_tf32(C[0][nt], a[0], b);
                mma_tf32(C[1][nt], a[1], b);
            }
        }

        if (s == 3) {
            // epilogue: bias add + store. Q fp32; K/V fp16 into g_KVh.
            const float* B = Bs[w];
#pragma unroll
            for (int nt = 0; nt < 8; ++nt) {
                int col = warpN * 64 + nt * 8 + 2 * tidx;
                float b0 = __ldg(B + col);
                float b1 = __ldg(B + col + 1);
#pragma unroll
                for (int mt = 0; mt < 2; ++mt) {
                    int r0 = row0 + warpM * 32 + mt * 16 + gidx;
                    int r1 = r0 + 8;
                    float o00 = C[mt][nt][0] + b0, o01 = C[mt][nt][1] + b1;
                    float o10 = C[mt][nt][2] + b0, o11 = C[mt][nt][3] + b1;
                    if (w == 0) {
                        if (r0 < n) *(float2*)(g_Q + (size_t)r0 * DD + col) =
                            make_float2(o00, o01);
                        if (r1 < n) *(float2*)(g_Q + (size_t)r1 * DD + col) =
                            make_float2(o10, o11);
                    } else {
                        int off = (w == 1) ? 0 : 128;
                        if (r0 < n)
                            *(__half2*)(g_KVh + (size_t)r0 * 256 + off + col) =
                                __floats2half2_rn(o00, o01);
                        if (r1 < n)
                            *(__half2*)(g_KVh + (size_t)r1 * 256 + off + col) =
                                __floats2half2_rn(o10, o11);
                    }
                }
            }
        }
        __syncthreads();   // done reading wb before it's refilled
    }
}

// ---------------- CSR construction -------------------------------------------
__global__ void hist_kernel(const int* __restrict__ dst, int E) {
    int i = blockIdx.x * blockDim.x + threadIdx.x;
    if (i < E) atomicAdd(&g_deg[dst[i]], 1);
}

// block-local exclusive scan; also zeroes g_deg for the next replay
__global__ __launch_bounds__(1024) void scan1(int n) {
    __shared__ int sm[1024];
    const int t = threadIdx.x;
    const int i = blockIdx.x * 1024 + t;
    int v = (i < n) ? g_deg[i] : 0;
    if (i < n) g_deg[i] = 0;
    sm[t] = v;
    __syncthreads();
    for (int off = 1; off < 1024; off <<= 1) {
        int u = (t >= off) ? sm[t - off] : 0;
        __syncthreads();
        sm[t] += u;
        __syncthreads();
    }
    if (i < n) g_rowptr[i] = sm[t] - v;
    if (t == 1023) g_bsum[blockIdx.x] = sm[t];
}

__global__ __launch_bounds__(1024) void scan3(int n, int E) {
    __shared__ int soff;
    const int t = threadIdx.x;
    if (t == 0) soff = 0;
    __syncthreads();
    int acc = 0;
    for (int j = t; j < blockIdx.x; j += 1024) acc += g_bsum[j];
    if (acc) atomicAdd(&soff, acc);
    __syncthreads();
    const int i = blockIdx.x * 1024 + t;
    if (i < n) {
        int r = g_rowptr[i] + soff;
        g_rowptr[i] = r;
        g_cursor[i] = r;
    }
    if (i == 0) g_rowptr[n] = E;
}

__global__ void scatter_kernel(const int* __restrict__ src,
                               const int* __restrict__ dst, int E) {
    int i = blockIdx.x * blockDim.x + threadIdx.x;
    if (i < E) {
        int p = atomicAdd(&g_cursor[dst[i]], 1);
        g_edge[p] = make_int2(i, src[i]);
    }
}

// ---------------- per-node online-softmax attention + normalization ----------
// One warp per node. Sweep 1: lane -> (head = lane/4, dim-quad = lane%4);
// scores go to g_scores in CSR order (sequential). Sweep 2: lane -> (edge
// quad = lane/8, head = lane%8); normalized attn written to attn_out[eid].
__global__ __launch_bounds__(256) void node_attn(
    const float* __restrict__ pi, const float* __restrict__ view_w,
    float* __restrict__ ns_out, float* __restrict__ attn_out, int n)
{
    int warp = (blockIdx.x * blockDim.x + threadIdx.x) >> 5;
    if (warp >= n) return;
    const int lane = threadIdx.x & 31;
    const int h = lane >> 2;
    const int nd = warp;
    const int dsub = lane & 3;

    const float4* Q4 = (const float4*)g_Q;
    const uint2* KVu = (const uint2*)g_KVh;   // 64 uint2 per node (512B)

    const float4 qv = Q4[nd * 32 + lane];
    const float p0 = pi[nd * 24 + h * 3 + 0];
    const float p1 = pi[nd * 24 + h * 3 + 1];
    const float p2 = pi[nd * 24 + h * 3 + 2];

    const int beg = g_rowptr[nd];
    const int end = g_rowptr[nd + 1];

    float m_run = -CUDART_INF_F;
    float s_run = 0.f;
    float ax = 0.f, ay = 0.f, az = 0.f, aw = 0.f;

    for (int j = beg; j < end; ++j) {
        const int2 e = g_edge[j];
        const int eid = e.x;
        const int sN = e.y;

        uint2 ku = KVu[(size_t)sN * 64 + lane];
        uint2 vu = KVu[(size_t)sN * 64 + 32 + lane];
        float2 k01 = __half22float2(*(__half2*)&ku.x);
        float2 k23 = __half22float2(*(__half2*)&ku.y);

        float d = qv.x * k01.x + qv.y * k01.y + qv.z * k23.x + qv.w * k23.y;
        d += __shfl_xor_sync(0xffffffff, d, 1);
        d += __shfl_xor_sync(0xffffffff, d, 2);

        float vw0 = view_w[eid * 3 + 0];
        float vw1 = view_w[eid * 3 + 1];
        float vw2 = view_w[eid * 3 + 2];
        float mix = p0 * vw0 + p1 * vw1 + p2 * vw2;

        float sc = d * 0.25f + __logf(fmaxf(mix, 1e-8f));
        if (!(mix > 0.f)) sc = -1e9f;
        if (dsub == 0) g_scores[(size_t)j * HH + h] = sc;   // sequential write

        float nm = fmaxf(m_run, sc);
        float scale = __expf(m_run - nm);
        float p = (sc > -1e8f) ? __expf(sc - nm) : 0.f;
        float2 v01 = __half22float2(*(__half2*)&vu.x);
        float2 v23 = __half22float2(*(__half2*)&vu.y);
        s_run = s_run * scale + p;
        ax = ax * scale + p * v01.x;
        ay = ay * scale + p * v01.y;
        az = az * scale + p * v23.x;
        aw = aw * scale + p * v23.y;
        m_run = nm;
    }

    float inv = 1.f / fmaxf(s_run, 1e-8f);
    ((float4*)ns_out)[nd * 32 + lane] = make_float4(ax * inv, ay * inv,
                                                    az * inv, aw * inv);

    // sweep 2: normalize scores -> attn_out. 4 edges per iteration.
    const int h2 = lane & 7;                 // head for sweep 2
    const float m_h = __shfl_sync(0xffffffff, m_run, h2 << 2);
    const float i_h = __shfl_sync(0xffffffff, inv,   h2 << 2);
    for (int j0 = beg; j0 < end; j0 += 4) {
        int j = j0 + (lane >> 3);
        if (j < end) {
            int eid = g_edge[j].x;
            float sc = g_scores[(size_t)j * HH + h2];   // coalesced read
            float a = (sc > -1e8f) ? __expf(sc - m_h) * i_h : 0.f;
            attn_out[(size_t)eid * HH + h2] = a;
        }
    }
}

// ---------------- launch ------------------------------------------------------
extern "C" void kernel_launch(void* const* d_in, const int* in_sizes, int n_in,
                              void* d_out, int out_size) {
    const float* x   = (const float*)d_in[0];
    const float* pi  = (const float*)d_in[1];
    const float* vw  = (const float*)d_in[2];
    const float* Wq  = (const float*)d_in[3];
    const float* bq  = (const float*)d_in[4];
    const float* Wk  = (const float*)d_in[5];
    const float* bk  = (const float*)d_in[6];
    const float* Wv  = (const float*)d_in[7];
    const float* bv  = (const float*)d_in[8];
    const int*   src = (const int*)d_in[9];
    const int*   dst = (const int*)d_in[10];

    const int n = in_sizes[0] / DD;   // 100000
    const int E = in_sizes[9];        // 1600000

    float* out = (float*)d_out;
    float* ns_out = out;                          // [n, H, DH]
    float* attn_out = out + (size_t)n * DD;       // [E, H]

    cudaFuncSetAttribute(qkv_gemm_tc, cudaFuncAttributeMaxDynamicSharedMemorySize,
                         GEMM_SMEM);

    const int nb = (n + 1023) / 1024;
    // g_deg starts zeroed (static init) and is re-zeroed by scan1 each replay.
    hist_kernel<<<(E + 255) / 256, 256>>>(dst, E);
    scan1<<<nb, 1024>>>(n);
    scan3<<<nb, 1024>>>(n, E);
    qkv_gemm_tc<<<(n + 127) / 128, 256, GEMM_SMEM>>>(x, Wq, bq, Wk, bk, Wv, bv, n);  // 4th: profiled
    scatter_kernel<<<(E + 255) / 256, 256>>>(src, dst, E);

    node_attn<<<(n + 7) / 8, 256>>>(pi, vw, ns_out, attn_out, n);
}